// round 4
// baseline (speedup 1.0000x reference)
#include <cuda_runtime.h>
#include <cuda_bf16.h>
#include <cstdint>

using bf16 = __nv_bfloat16;

#define B_ 8
#define N_ 1024
#define D_ 512
#define MLP_ 2048
#define ROWS_ (B_ * N_)
#define NEGBIG (-1e10f)
#define NINF __int_as_float(0xff800000)

// ---------------- scratch ----------------
__device__ bf16  g_h[ROWS_ * D_];
__device__ bf16  g_qkv[ROWS_ * 3 * D_];
__device__ bf16  g_attn[ROWS_ * D_];
__device__ float g_x1[ROWS_ * D_];
__device__ float g_h2f[ROWS_ * D_];
__device__ float g_fff[ROWS_ * MLP_];
__device__ float g_topk[B_ * N_];
__device__ uint32_t g_mbits[B_ * N_ * 32];
__device__ bf16  g_Wqkv[D_ * 3 * D_];
__device__ bf16  g_Wout[D_ * D_];

// ---------------- helpers ----------------
__device__ __forceinline__ void mma16816(float* c, const uint32_t* a, uint32_t b0, uint32_t b1) {
    asm volatile("mma.sync.aligned.m16n8k16.row.col.f32.bf16.bf16.f32 "
                 "{%0,%1,%2,%3},{%4,%5,%6,%7},{%8,%9},{%0,%1,%2,%3};\n"
                 : "+f"(c[0]), "+f"(c[1]), "+f"(c[2]), "+f"(c[3])
                 : "r"(a[0]), "r"(a[1]), "r"(a[2]), "r"(a[3]), "r"(b0), "r"(b1));
}
__device__ __forceinline__ void mma1688t(float* c, const uint32_t* a, uint32_t b0, uint32_t b1) {
    asm volatile("mma.sync.aligned.m16n8k8.row.col.f32.tf32.tf32.f32 "
                 "{%0,%1,%2,%3},{%4,%5,%6,%7},{%8,%9},{%0,%1,%2,%3};\n"
                 : "+f"(c[0]), "+f"(c[1]), "+f"(c[2]), "+f"(c[3])
                 : "r"(a[0]), "r"(a[1]), "r"(a[2]), "r"(a[3]), "r"(b0), "r"(b1));
}
__device__ __forceinline__ void ldsm4(uint32_t* r, uint32_t a) {
    asm volatile("ldmatrix.sync.aligned.m8n8.x4.shared.b16 {%0,%1,%2,%3},[%4];"
                 : "=r"(r[0]), "=r"(r[1]), "=r"(r[2]), "=r"(r[3]) : "r"(a));
}
__device__ __forceinline__ void ldsm4t(uint32_t* r, uint32_t a) {
    asm volatile("ldmatrix.sync.aligned.m8n8.x4.trans.shared.b16 {%0,%1,%2,%3},[%4];"
                 : "=r"(r[0]), "=r"(r[1]), "=r"(r[2]), "=r"(r[3]) : "r"(a));
}
__device__ __forceinline__ uint32_t packbf(float x, float y) {
    __nv_bfloat162 t = __floats2bfloat162_rn(x, y);
    return *(uint32_t*)&t;
}
__device__ __forceinline__ float totf32(float x) {
    uint32_t r;
    asm("cvt.rna.tf32.f32 %0, %1;" : "=r"(r) : "f"(x));
    return __uint_as_float(r);
}

__global__ void cvt_kernel(const float* __restrict__ s, bf16* __restrict__ d, int n) {
    int i = blockIdx.x * blockDim.x + threadIdx.x;
    if (i < n) d[i] = __float2bfloat16(s[i]);
}

__global__ void maskbits_kernel(const float* __restrict__ mask, uint32_t* __restrict__ bits) {
    int idx = blockIdx.x * blockDim.x + threadIdx.x;
    uint32_t bal = __ballot_sync(0xffffffffu, mask[idx] == 1.0f);
    if ((idx & 31) == 0) bits[idx >> 5] = bal;
}

// ---------------- LayerNorm (BF: bf16 out, else fp32 out) ----------------
template<bool BF>
__global__ void __launch_bounds__(128) ln_kernel(const float* __restrict__ x,
                                                 const float* __restrict__ gam,
                                                 const float* __restrict__ bet,
                                                 void* __restrict__ out) {
    int row = blockIdx.x, t = threadIdx.x;
    float4 a = ((const float4*)(x + (size_t)row * D_))[t];
    float s = a.x + a.y + a.z + a.w;
    float sq = a.x * a.x + a.y * a.y + a.z * a.z + a.w * a.w;
    __shared__ float sh[8];
    #pragma unroll
    for (int o = 16; o > 0; o >>= 1) {
        s += __shfl_down_sync(0xffffffffu, s, o);
        sq += __shfl_down_sync(0xffffffffu, sq, o);
    }
    int w = t >> 5;
    if ((t & 31) == 0) { sh[w] = s; sh[4 + w] = sq; }
    __syncthreads();
    if (t == 0) {
        float S = sh[0] + sh[1] + sh[2] + sh[3];
        float Q = sh[4] + sh[5] + sh[6] + sh[7];
        float mu = S * (1.0f / D_);
        sh[0] = mu; sh[1] = rsqrtf(Q * (1.0f / D_) - mu * mu + 1e-5f);
    }
    __syncthreads();
    float mu = sh[0], rs = sh[1];
    float4 gv = ((const float4*)gam)[t];
    float4 bv = ((const float4*)bet)[t];
    float o0 = (a.x - mu) * rs * gv.x + bv.x;
    float o1 = (a.y - mu) * rs * gv.y + bv.y;
    float o2 = (a.z - mu) * rs * gv.z + bv.z;
    float o3 = (a.w - mu) * rs * gv.w + bv.w;
    if (BF) {
        bf16* o = (bf16*)out + (size_t)row * D_ + t * 4;
        ((__nv_bfloat162*)o)[0] = __floats2bfloat162_rn(o0, o1);
        ((__nv_bfloat162*)o)[1] = __floats2bfloat162_rn(o2, o3);
    } else {
        ((float4*)((float*)out + (size_t)row * D_))[t] = make_float4(o0, o1, o2, o3);
    }
}

// ---------------- flash attention: grid(8 mtiles, 64 bh), 256 thr ----------------
#define LQ 72
__global__ void __launch_bounds__(256) flash_kernel(const bf16* __restrict__ qkv,
                                                    const uint32_t* __restrict__ mbits,
                                                    bf16* __restrict__ attn) {
    __shared__ bf16 Qs[128 * LQ];
    __shared__ bf16 KVs[128 * LQ];
    __shared__ uint32_t mwords[512];

    int bh = blockIdx.y, b = bh >> 3, h = bh & 7;
    int tid = threadIdx.x, w = tid >> 5, lane = tid & 31, g = lane >> 2, tg = lane & 3;
    int q0 = blockIdx.x * 128;
    size_t base = (size_t)b * N_ * 1536;
    uint32_t sQ = (uint32_t)__cvta_generic_to_shared(Qs);
    uint32_t sKV = (uint32_t)__cvta_generic_to_shared(KVs);

    for (int c = tid; c < 1024; c += 256) {
        int r = c >> 3, d0 = (c & 7) * 8;
        *(uint4*)&Qs[r * LQ + d0] =
            *(const uint4*)(qkv + base + (size_t)(q0 + r) * 1536 + h * 64 + d0);
    }
    float Oa[8][4];
    #pragma unroll
    for (int i = 0; i < 8; i++)
        #pragma unroll
        for (int j = 0; j < 4; j++) Oa[i][j] = 0.0f;
    float mrow0 = NINF, mrow1 = NINF, lrow0 = 0.0f, lrow1 = 0.0f;
    __syncthreads();

    int aRow = w * 16 + ((lane >> 3) & 1) * 8 + (lane & 7);
    int aSel = (lane >> 4) * 8;
    int bRowOff = (lane >> 4) * 8 + (lane & 7);
    int bSel = ((lane >> 3) & 1) * 8;
    int vKeyOff = ((lane >> 3) & 1) * 8 + (lane & 7);
    int vDSel = (lane >> 4);

    for (int kt = 0; kt < 8; kt++) {
        for (int c = tid; c < 1024; c += 256) {
            int r = c >> 3, d0 = (c & 7) * 8;
            *(uint4*)&KVs[r * LQ + d0] =
                *(const uint4*)(qkv + base + (size_t)(kt * 128 + r) * 1536 + 512 + h * 64 + d0);
        }
        for (int c = tid; c < 512; c += 256)
            mwords[c] = mbits[((size_t)b * N_ + q0 + (c >> 2)) * 32 + kt * 4 + (c & 3)];
        __syncthreads();

        float sacc[16][4];
        #pragma unroll
        for (int nf = 0; nf < 16; nf++)
            #pragma unroll
            for (int j = 0; j < 4; j++) sacc[nf][j] = 0.0f;
        #pragma unroll
        for (int kk = 0; kk < 64; kk += 16) {
            uint32_t aq[4];
            ldsm4(aq, sQ + (uint32_t)(aRow * LQ + kk + aSel) * 2);
            #pragma unroll
            for (int nfp = 0; nfp < 8; nfp++) {
                uint32_t bq[4];
                ldsm4(bq, sKV + (uint32_t)((nfp * 16 + bRowOff) * LQ + kk + bSel) * 2);
                mma16816(sacc[2 * nfp], aq, bq[0], bq[1]);
                mma16816(sacc[2 * nfp + 1], aq, bq[2], bq[3]);
            }
        }

        int r0l = w * 16 + g;
        uint32_t mwa[4], mwb[4];
        #pragma unroll
        for (int i = 0; i < 4; i++) {
            mwa[i] = mwords[r0l * 4 + i];
            mwb[i] = mwords[(r0l + 8) * 4 + i];
        }
        float mx0 = -3e38f, mx1 = -3e38f;
        #pragma unroll
        for (int nf = 0; nf < 16; nf++) {
            int c0 = nf * 8 + 2 * tg;
            uint32_t wa = mwa[c0 >> 5], wb = mwb[c0 >> 5];
            int shm = c0 & 31;
            float s00 = ((wa >> shm) & 1) ? NEGBIG : sacc[nf][0] * 0.125f;
            float s01 = ((wa >> (shm + 1)) & 1) ? NEGBIG : sacc[nf][1] * 0.125f;
            float s10 = ((wb >> shm) & 1) ? NEGBIG : sacc[nf][2] * 0.125f;
            float s11 = ((wb >> (shm + 1)) & 1) ? NEGBIG : sacc[nf][3] * 0.125f;
            sacc[nf][0] = s00; sacc[nf][1] = s01; sacc[nf][2] = s10; sacc[nf][3] = s11;
            mx0 = fmaxf(mx0, fmaxf(s00, s01));
            mx1 = fmaxf(mx1, fmaxf(s10, s11));
        }
        mx0 = fmaxf(mx0, __shfl_xor_sync(0xffffffffu, mx0, 1));
        mx0 = fmaxf(mx0, __shfl_xor_sync(0xffffffffu, mx0, 2));
        mx1 = fmaxf(mx1, __shfl_xor_sync(0xffffffffu, mx1, 1));
        mx1 = fmaxf(mx1, __shfl_xor_sync(0xffffffffu, mx1, 2));
        float mn0 = fmaxf(mrow0, mx0), mn1 = fmaxf(mrow1, mx1);
        float cf0 = __expf(mrow0 - mn0), cf1 = __expf(mrow1 - mn1);
        mrow0 = mn0; mrow1 = mn1;
        float rs0 = 0.0f, rs1 = 0.0f;
        #pragma unroll
        for (int nf = 0; nf < 16; nf++) {
            float p00 = __expf(sacc[nf][0] - mn0);
            float p01 = __expf(sacc[nf][1] - mn0);
            float p10 = __expf(sacc[nf][2] - mn1);
            float p11 = __expf(sacc[nf][3] - mn1);
            sacc[nf][0] = p00; sacc[nf][1] = p01; sacc[nf][2] = p10; sacc[nf][3] = p11;
            rs0 += p00 + p01; rs1 += p10 + p11;
        }
        rs0 += __shfl_xor_sync(0xffffffffu, rs0, 1);
        rs0 += __shfl_xor_sync(0xffffffffu, rs0, 2);
        rs1 += __shfl_xor_sync(0xffffffffu, rs1, 1);
        rs1 += __shfl_xor_sync(0xffffffffu, rs1, 2);
        lrow0 = lrow0 * cf0 + rs0;
        lrow1 = lrow1 * cf1 + rs1;
        #pragma unroll
        for (int df = 0; df < 8; df++) {
            Oa[df][0] *= cf0; Oa[df][1] *= cf0;
            Oa[df][2] *= cf1; Oa[df][3] *= cf1;
        }
        uint32_t pa[8][4];
        #pragma unroll
        for (int f = 0; f < 8; f++) {
            pa[f][0] = packbf(sacc[2 * f][0], sacc[2 * f][1]);
            pa[f][1] = packbf(sacc[2 * f][2], sacc[2 * f][3]);
            pa[f][2] = packbf(sacc[2 * f + 1][0], sacc[2 * f + 1][1]);
            pa[f][3] = packbf(sacc[2 * f + 1][2], sacc[2 * f + 1][3]);
        }
        __syncthreads();
        for (int c = tid; c < 1024; c += 256) {
            int r = c >> 3, d0 = (c & 7) * 8;
            *(uint4*)&KVs[r * LQ + d0] =
                *(const uint4*)(qkv + base + (size_t)(kt * 128 + r) * 1536 + 1024 + h * 64 + d0);
        }
        __syncthreads();
        #pragma unroll
        for (int f = 0; f < 8; f++) {
            #pragma unroll
            for (int q = 0; q < 4; q++) {
                uint32_t bv[4];
                ldsm4t(bv, sKV + (uint32_t)((f * 16 + vKeyOff) * LQ + (vDSel + 2 * q) * 8) * 2);
                mma16816(Oa[2 * q], pa[f], bv[0], bv[1]);
                mma16816(Oa[2 * q + 1], pa[f], bv[2], bv[3]);
            }
        }
        __syncthreads();
    }

    float inv0 = 1.0f / lrow0, inv1 = 1.0f / lrow1;
    int orow = b * N_ + q0 + w * 16 + g;
    #pragma unroll
    for (int df = 0; df < 8; df++) {
        int col = h * 64 + df * 8 + 2 * tg;
        *(__nv_bfloat162*)(attn + (size_t)orow * 512 + col) =
            __floats2bfloat162_rn(Oa[df][0] * inv0, Oa[df][1] * inv0);
        *(__nv_bfloat162*)(attn + (size_t)(orow + 8) * 512 + col) =
            __floats2bfloat162_rn(Oa[df][2] * inv1, Oa[df][3] * inv1);
    }
}

// ---------------- att_topk from softmax row 0 ----------------
__device__ __forceinline__ float blkmax(float v, float* red, int tid) {
    #pragma unroll
    for (int o = 16; o > 0; o >>= 1) v = fmaxf(v, __shfl_xor_sync(0xffffffffu, v, o));
    if ((tid & 31) == 0) red[tid >> 5] = v;
    __syncthreads();
    if (tid < 32) {
        float t = red[tid];
        #pragma unroll
        for (int o = 16; o > 0; o >>= 1) t = fmaxf(t, __shfl_xor_sync(0xffffffffu, t, o));
        if (tid == 0) red[0] = t;
    }
    __syncthreads();
    float r = red[0];
    __syncthreads();
    return r;
}
__device__ __forceinline__ float blksum(float v, float* red, int tid) {
    #pragma unroll
    for (int o = 16; o > 0; o >>= 1) v += __shfl_xor_sync(0xffffffffu, v, o);
    if ((tid & 31) == 0) red[tid >> 5] = v;
    __syncthreads();
    if (tid < 32) {
        float t = red[tid];
        #pragma unroll
        for (int o = 16; o > 0; o >>= 1) t += __shfl_xor_sync(0xffffffffu, t, o);
        if (tid == 0) red[0] = t;
    }
    __syncthreads();
    float r = red[0];
    __syncthreads();
    return r;
}
__global__ void __launch_bounds__(1024) topk0_kernel(const bf16* __restrict__ qkv,
                                                     const float* __restrict__ mask,
                                                     float* __restrict__ topk) {
    int b = blockIdx.x, m = threadIdx.x;
    __shared__ float q0s[512];
    __shared__ float red[32];
    size_t rb = (size_t)b * N_ * 1536;
    if (m < 512) q0s[m] = __bfloat162float(qkv[rb + m]);
    __syncthreads();
    const bf16* krow = qkv + rb + (size_t)m * 1536 + 512;
    float s[8];
    #pragma unroll
    for (int h = 0; h < 8; h++) {
        float acc = 0.0f;
        #pragma unroll
        for (int j = 0; j < 64; j += 8) {
            uint4 kv = *(const uint4*)(krow + h * 64 + j);
            bf16 t[8]; *(uint4*)t = kv;
            #pragma unroll
            for (int i = 0; i < 8; i++) acc += q0s[h * 64 + j + i] * __bfloat162float(t[i]);
        }
        s[h] = acc * 0.125f;
    }
    if (mask[(size_t)b * N_ * N_ + m] == 1.0f)
        #pragma unroll
        for (int h = 0; h < 8; h++) s[h] = NEGBIG;
    float out = 0.0f;
    #pragma unroll
    for (int h = 0; h < 8; h++) {
        float M = blkmax(s[h], red, m);
        float p = __expf(s[h] - M);
        float L = blksum(p, red, m);
        out += p / L;
    }
    topk[b * N_ + m] = out * 0.125f;
}

__global__ void __launch_bounds__(1024) prune_kernel(const float* __restrict__ topk,
                                                     float* __restrict__ out) {
    int b = blockIdx.x, m = threadIdx.x;
    __shared__ float key[N_];
    float km = (m == 0) ? NINF : topk[b * N_ + m];
    key[m] = km;
    __syncthreads();
    int rank = 0;
    for (int j = 0; j < N_; j++) {
        float kj = key[j];
        rank += (kj > km) || (kj == km && j < m);
    }
    if (rank >= 959 && rank < 1023) out[4194304 + b * 64 + (rank - 959)] = (float)m;
    if (m == 0) out[4194816 + b] = -1.0f;
    if (m < 16) out[4194824 + b * 16 + m] = 0.0f;
}

// ---------------- bf16 GEMM. EPI: 0=bf16 store, 2=+bias+resid->fp32 -------------
template<int EPI>
__global__ void __launch_bounds__(256) gemm_k(
    const bf16* __restrict__ A, const bf16* __restrict__ Bm, void* __restrict__ Cp,
    int K, int lda, int ldb, int ldc,
    const float* __restrict__ bias, const float* __restrict__ resid)
{
    constexpr int BM = 128, BN = 128, BK = 32, LDS = 40;
    __shared__ bf16 As[BM * LDS];
    __shared__ bf16 Bs[BN * LDS];
    int tid = threadIdx.x, warp = tid >> 5, lane = tid & 31;
    int g = lane >> 2, tg = lane & 3;
    int warpM = warp & 3, warpN = warp >> 2;
    int row0 = blockIdx.y * BM, col0 = blockIdx.x * BN;

    float acc[2][8][4];
    #pragma unroll
    for (int a = 0; a < 2; a++)
        #pragma unroll
        for (int b2 = 0; b2 < 8; b2++)
            #pragma unroll
            for (int c = 0; c < 4; c++) acc[a][b2][c] = 0.0f;

    for (int k0 = 0; k0 < K; k0 += BK) {
        for (int c = tid; c < 512; c += 256) {
            int r = c >> 2, kc = (c & 3) << 3;
            *(uint4*)(&As[r * LDS + kc]) =
                *(const uint4*)(A + (size_t)(row0 + r) * lda + k0 + kc);
        }
        for (int c = tid; c < 512; c += 256) {
            int kk = c >> 4, nc = (c & 15) << 3;
            uint4 vv = *(const uint4*)(Bm + (size_t)(k0 + kk) * ldb + col0 + nc);
            bf16 tmp[8]; *(uint4*)tmp = vv;
            #pragma unroll
            for (int i = 0; i < 8; i++) Bs[(nc + i) * LDS + kk] = tmp[i];
        }
        __syncthreads();
        #pragma unroll
        for (int kk = 0; kk < BK; kk += 16) {
            uint32_t af[2][4], bfr[8][2];
            #pragma unroll
            for (int mt = 0; mt < 2; mt++) {
                const bf16* p = &As[(warpM * 32 + mt * 16 + g) * LDS + kk + 2 * tg];
                af[mt][0] = *(const uint32_t*)p;
                af[mt][1] = *(const uint32_t*)(p + 8 * LDS);
                af[mt][2] = *(const uint32_t*)(p + 8);
                af[mt][3] = *(const uint32_t*)(p + 8 * LDS + 8);
            }
            #pragma unroll
            for (int nt = 0; nt < 8; nt++) {
                const bf16* p = &Bs[(warpN * 64 + nt * 8 + g) * LDS + kk + 2 * tg];
                bfr[nt][0] = *(const uint32_t*)p;
                bfr[nt][1] = *(const uint32_t*)(p + 8);
            }
            #pragma unroll
            for (int mt = 0; mt < 2; mt++)
                #pragma unroll
                for (int nt = 0; nt < 8; nt++)
                    mma16816(acc[mt][nt], af[mt], bfr[nt][0], bfr[nt][1]);
        }
        __syncthreads();
    }
    #pragma unroll
    for (int mt = 0; mt < 2; mt++)
        #pragma unroll
        for (int nt = 0; nt < 8; nt++) {
            int r = row0 + warpM * 32 + mt * 16 + g;
            int cc = col0 + warpN * 64 + nt * 8 + 2 * tg;
            #pragma unroll
            for (int hf = 0; hf < 2; hf++) {
                int rr = r + hf * 8;
                float v0 = acc[mt][nt][hf * 2], v1 = acc[mt][nt][hf * 2 + 1];
                long idx = (long)rr * ldc + cc;
                if (EPI == 0) {
                    *(__nv_bfloat162*)((bf16*)Cp + idx) = __floats2bfloat162_rn(v0, v1);
                } else {
                    v0 += bias[cc] + resid[idx];
                    v1 += bias[cc + 1] + resid[idx + 1];
                    *(float2*)((float*)Cp + idx) = make_float2(v0, v1);
                }
            }
        }
}

// ---------------- tf32 GEMM. EPI: 2=+bias+resid, 3=gelu(.+bias) -------------
template<int EPI>
__global__ void __launch_bounds__(256) gemm_tf32(
    const float* __restrict__ A, const float* __restrict__ Bm, float* __restrict__ C,
    int K, int lda, int ldb, int ldc,
    const float* __restrict__ bias, const float* __restrict__ resid)
{
    constexpr int BM = 128, BN = 128, BK = 32, LA = 36;
    __shared__ float As[BM * LA];
    __shared__ float Bs[BN * LA];
    int tid = threadIdx.x, warp = tid >> 5, lane = tid & 31;
    int g = lane >> 2, tg = lane & 3;
    int warpM = warp & 3, warpN = warp >> 2;
    int row0 = blockIdx.y * BM, col0 = blockIdx.x * BN;

    float acc[2][8][4];
    #pragma unroll
    for (int a = 0; a < 2; a++)
        #pragma unroll
        for (int b2 = 0; b2 < 8; b2++)
            #pragma unroll
            for (int c = 0; c < 4; c++) acc[a][b2][c] = 0.0f;

    for (int k0 = 0; k0 < K; k0 += BK) {
        for (int c = tid; c < 1024; c += 256) {
            int r = c >> 3, j = (c & 7) * 4;
            float4 v = *(const float4*)(A + (size_t)(row0 + r) * lda + k0 + j);
            *(float4*)&As[r * LA + j] =
                make_float4(totf32(v.x), totf32(v.y), totf32(v.z), totf32(v.w));
        }
        for (int c = tid; c < 1024; c += 256) {
            int n = c & 127, k4 = (c >> 7) * 4;
            #pragma unroll
            for (int i = 0; i < 4; i++)
                Bs[n * LA + k4 + i] = totf32(Bm[(size_t)(k0 + k4 + i) * ldb + col0 + n]);
        }
        __syncthreads();
        #pragma unroll
        for (int kk = 0; kk < BK; kk += 8) {
            uint32_t af[2][4], bfr[8][2];
            #pragma unroll
            for (int mt = 0; mt < 2; mt++) {
                int rb = warpM * 32 + mt * 16 + g;
                af[mt][0] = *(const uint32_t*)&As[rb * LA + kk + tg];
                af[mt][1] = *(const uint32_t*)&As[(rb + 8) * LA + kk + tg];
                af[mt][2] = *(const uint32_t*)&As[rb * LA + kk + tg + 4];
                af[mt][3] = *(const uint32_t*)&As[(rb + 8) * LA + kk + tg + 4];
            }
            #pragma unroll
            for (int nt = 0; nt < 8; nt++) {
                int nb = warpN * 64 + nt * 8 + g;
                bfr[nt][0] = *(const uint32_t*)&Bs[nb * LA + kk + tg];
                bfr[nt][1] = *(const uint32_t*)&Bs[nb * LA + kk + tg + 4];
            }
            #pragma unroll
            for (int mt = 0; mt < 2; mt++)
                #pragma unroll
                for (int nt = 0; nt < 8; nt++)
                    mma1688t(acc[mt][nt], af[mt], bfr[nt][0], bfr[nt][1]);
        }
        __syncthreads();
    }
    #pragma unroll
    for (int mt = 0; mt < 2; mt++)
        #pragma unroll
        for (int nt = 0; nt < 8; nt++) {
            int r = row0 + warpM * 32 + mt * 16 + g;
            int cc = col0 + warpN * 64 + nt * 8 + 2 * tg;
            #pragma unroll
            for (int hf = 0; hf < 2; hf++) {
                int rr = r + hf * 8;
                float v0 = acc[mt][nt][hf * 2], v1 = acc[mt][nt][hf * 2 + 1];
                long idx = (long)rr * ldc + cc;
                if (EPI == 2) {
                    v0 += bias[cc] + resid[idx];
                    v1 += bias[cc + 1] + resid[idx + 1];
                } else {
                    v0 += bias[cc]; v1 += bias[cc + 1];
                    v0 = 0.5f * v0 * (1.0f + erff(v0 * 0.70710678f));
                    v1 = 0.5f * v1 * (1.0f + erff(v1 * 0.70710678f));
                }
                *(float2*)(C + idx) = make_float2(v0, v1);
            }
        }
}

// ---------------- host ----------------
template <typename T>
static T* symaddr(const T& sym) {
    void* p = nullptr;
    cudaGetSymbolAddress(&p, sym);
    return (T*)p;
}

extern "C" void kernel_launch(void* const* d_in, const int* in_sizes, int n_in,
                              void* d_out, int out_size) {
    const float* x    = (const float*)d_in[0];
    const float* mask = (const float*)d_in[1];
    const float* Wqkv = (const float*)d_in[2];
    const float* Wout = (const float*)d_in[3];
    const float* bout = (const float*)d_in[4];
    const float* ln1g = (const float*)d_in[5];
    const float* ln1b = (const float*)d_in[6];
    const float* ln2g = (const float*)d_in[7];
    const float* ln2b = (const float*)d_in[8];
    const float* W1   = (const float*)d_in[9];
    const float* b1   = (const float*)d_in[10];
    const float* W2   = (const float*)d_in[11];
    const float* b2   = (const float*)d_in[12];

    bf16* h = (bf16*)symaddr(g_h);
    bf16* qkv = (bf16*)symaddr(g_qkv);
    bf16* attn = (bf16*)symaddr(g_attn);
    float* x1 = (float*)symaddr(g_x1);
    float* h2f = (float*)symaddr(g_h2f);
    float* fff = (float*)symaddr(g_fff);
    float* tk = (float*)symaddr(g_topk);
    uint32_t* mb = (uint32_t*)symaddr(g_mbits);
    bf16* wqkv = (bf16*)symaddr(g_Wqkv);
    bf16* wout = (bf16*)symaddr(g_Wout);

    cvt_kernel<<<(D_ * 3 * D_ + 255) / 256, 256>>>(Wqkv, wqkv, D_ * 3 * D_);
    cvt_kernel<<<(D_ * D_ + 255) / 256, 256>>>(Wout, wout, D_ * D_);
    maskbits_kernel<<<B_ * N_ * N_ / 256, 256>>>(mask, mb);
    ln_kernel<true><<<ROWS_, 128>>>(x, ln1g, ln1b, h);

    // qkv = h @ Wqkv
    gemm_k<0><<<dim3(12, 64), 256>>>(h, wqkv, qkv, D_, D_, 3 * D_, 3 * D_, nullptr, nullptr);
    // fused attention
    flash_kernel<<<dim3(8, 64), 256>>>(qkv, mb, attn);
    // prune outputs
    topk0_kernel<<<B_, 1024>>>(qkv, mask, tk);
    prune_kernel<<<B_, 1024>>>(tk, (float*)d_out);
    // x1 = x + attn @ Wout + bout
    gemm_k<2><<<dim3(4, 64), 256>>>(attn, wout, x1, D_, D_, D_, D_, bout, x);
    ln_kernel<false><<<ROWS_, 128>>>(x1, ln2g, ln2b, h2f);
    // ff = gelu(h2 @ W1 + b1)   [tf32]
    gemm_tf32<3><<<dim3(16, 64), 256>>>(h2f, W1, fff, D_, D_, MLP_, MLP_, b1, nullptr);
    // out = x1 + ff @ W2 + b2   [tf32]
    gemm_tf32<2><<<dim3(4, 64), 256>>>(fff, W2, (float*)d_out, MLP_, MLP_, D_, D_, b2, x1);
}

// round 5
// speedup vs baseline: 1.9234x; 1.9234x over previous
#include <cuda_runtime.h>
#include <cuda_bf16.h>
#include <cstdint>

using bf16 = __nv_bfloat16;

#define B_ 8
#define N_ 1024
#define D_ 512
#define MLP_ 2048
#define ROWS_ (B_ * N_)
#define NEGBIG (-1e10f)
#define NINF __int_as_float(0xff800000)

// ---------------- scratch ----------------
__device__ bf16  g_h[ROWS_ * D_];
__device__ bf16  g_qkv[ROWS_ * 3 * D_];
__device__ bf16  g_attn[ROWS_ * D_];
__device__ float g_x1[ROWS_ * D_];
__device__ float g_h2f[ROWS_ * D_];
__device__ float g_fff[ROWS_ * MLP_];
__device__ float g_topk[B_ * N_];
__device__ uint32_t g_mbits[B_ * N_ * 32];
__device__ bf16  g_Wqkv[D_ * 3 * D_];
__device__ bf16  g_Wout[D_ * D_];

// ---------------- helpers ----------------
__device__ __forceinline__ void mma16816(float* c, const uint32_t* a, uint32_t b0, uint32_t b1) {
    asm volatile("mma.sync.aligned.m16n8k16.row.col.f32.bf16.bf16.f32 "
                 "{%0,%1,%2,%3},{%4,%5,%6,%7},{%8,%9},{%0,%1,%2,%3};\n"
                 : "+f"(c[0]), "+f"(c[1]), "+f"(c[2]), "+f"(c[3])
                 : "r"(a[0]), "r"(a[1]), "r"(a[2]), "r"(a[3]), "r"(b0), "r"(b1));
}
__device__ __forceinline__ void mma1688t(float* c, const uint32_t* a, uint32_t b0, uint32_t b1) {
    asm volatile("mma.sync.aligned.m16n8k8.row.col.f32.tf32.tf32.f32 "
                 "{%0,%1,%2,%3},{%4,%5,%6,%7},{%8,%9},{%0,%1,%2,%3};\n"
                 : "+f"(c[0]), "+f"(c[1]), "+f"(c[2]), "+f"(c[3])
                 : "r"(a[0]), "r"(a[1]), "r"(a[2]), "r"(a[3]), "r"(b0), "r"(b1));
}
__device__ __forceinline__ void ldsm4(uint32_t* r, uint32_t a) {
    asm volatile("ldmatrix.sync.aligned.m8n8.x4.shared.b16 {%0,%1,%2,%3},[%4];"
                 : "=r"(r[0]), "=r"(r[1]), "=r"(r[2]), "=r"(r[3]) : "r"(a));
}
__device__ __forceinline__ void ldsm4t(uint32_t* r, uint32_t a) {
    asm volatile("ldmatrix.sync.aligned.m8n8.x4.trans.shared.b16 {%0,%1,%2,%3},[%4];"
                 : "=r"(r[0]), "=r"(r[1]), "=r"(r[2]), "=r"(r[3]) : "r"(a));
}
__device__ __forceinline__ uint32_t packbf(float x, float y) {
    __nv_bfloat162 t = __floats2bfloat162_rn(x, y);
    return *(uint32_t*)&t;
}
__device__ __forceinline__ void cp16(uint32_t s, const void* g) {
    asm volatile("cp.async.cg.shared.global [%0],[%1],16;\n" :: "r"(s), "l"(g));
}
__device__ __forceinline__ void cp4(uint32_t s, const void* g) {
    asm volatile("cp.async.ca.shared.global [%0],[%1],4;\n" :: "r"(s), "l"(g));
}
__device__ __forceinline__ void cpcommit() { asm volatile("cp.async.commit_group;\n"); }
__device__ __forceinline__ void cpwait0() { asm volatile("cp.async.wait_group 0;\n"); }
__device__ __forceinline__ void cpwait1() { asm volatile("cp.async.wait_group 1;\n"); }

__global__ void cvt_kernel(const float* __restrict__ s, bf16* __restrict__ d, int n) {
    int i = blockIdx.x * blockDim.x + threadIdx.x;
    if (i < n) d[i] = __float2bfloat16(s[i]);
}

__global__ void maskbits_kernel(const float* __restrict__ mask, uint32_t* __restrict__ bits) {
    int idx = blockIdx.x * blockDim.x + threadIdx.x;
    uint32_t bal = __ballot_sync(0xffffffffu, mask[idx] == 1.0f);
    if ((idx & 31) == 0) bits[idx >> 5] = bal;
}

// ---------------- LayerNorm ----------------
template<bool BF>
__global__ void __launch_bounds__(128) ln_kernel(const float* __restrict__ x,
                                                 const float* __restrict__ gam,
                                                 const float* __restrict__ bet,
                                                 void* __restrict__ out) {
    int row = blockIdx.x, t = threadIdx.x;
    float4 a = ((const float4*)(x + (size_t)row * D_))[t];
    float s = a.x + a.y + a.z + a.w;
    float sq = a.x * a.x + a.y * a.y + a.z * a.z + a.w * a.w;
    __shared__ float sh[8];
    #pragma unroll
    for (int o = 16; o > 0; o >>= 1) {
        s += __shfl_down_sync(0xffffffffu, s, o);
        sq += __shfl_down_sync(0xffffffffu, sq, o);
    }
    int w = t >> 5;
    if ((t & 31) == 0) { sh[w] = s; sh[4 + w] = sq; }
    __syncthreads();
    if (t == 0) {
        float S = sh[0] + sh[1] + sh[2] + sh[3];
        float Q = sh[4] + sh[5] + sh[6] + sh[7];
        float mu = S * (1.0f / D_);
        sh[0] = mu; sh[1] = rsqrtf(Q * (1.0f / D_) - mu * mu + 1e-5f);
    }
    __syncthreads();
    float mu = sh[0], rs = sh[1];
    float4 gv = ((const float4*)gam)[t];
    float4 bv = ((const float4*)bet)[t];
    float o0 = (a.x - mu) * rs * gv.x + bv.x;
    float o1 = (a.y - mu) * rs * gv.y + bv.y;
    float o2 = (a.z - mu) * rs * gv.z + bv.z;
    float o3 = (a.w - mu) * rs * gv.w + bv.w;
    if (BF) {
        bf16* o = (bf16*)out + (size_t)row * D_ + t * 4;
        ((__nv_bfloat162*)o)[0] = __floats2bfloat162_rn(o0, o1);
        ((__nv_bfloat162*)o)[1] = __floats2bfloat162_rn(o2, o3);
    } else {
        ((float4*)((float*)out + (size_t)row * D_))[t] = make_float4(o0, o1, o2, o3);
    }
}

// ---------------- flash attention, cp.async pipelined ----------------
#define LQ 72
#define FL_SMEM (3 * 128 * LQ * 2 + 2 * 512 * 4)   // 59392
__global__ void __launch_bounds__(256) flash_kernel(const bf16* __restrict__ qkv,
                                                    const uint32_t* __restrict__ mbits,
                                                    bf16* __restrict__ attn) {
    extern __shared__ char sm[];
    uint32_t sQ = (uint32_t)__cvta_generic_to_shared(sm);
    uint32_t sK = sQ + 128 * LQ * 2;
    uint32_t sV = sK + 128 * LQ * 2;
    uint32_t sM = sV + 128 * LQ * 2;
    uint32_t* mw = (uint32_t*)(sm + 3 * 128 * LQ * 2);

    int bh = blockIdx.y, b = bh >> 3, h = bh & 7;
    int tid = threadIdx.x, w = tid >> 5, lane = tid & 31, g = lane >> 2, tg = lane & 3;
    int q0 = blockIdx.x * 128;
    size_t base = (size_t)b * N_ * 1536;

    // prologue: Q, K0, mask0
    #pragma unroll
    for (int it = 0, c = tid; it < 4; it++, c += 256) {
        int r = c >> 3, d0 = (c & 7) * 8;
        cp16(sQ + (r * LQ + d0) * 2, qkv + base + (size_t)(q0 + r) * 1536 + h * 64 + d0);
        cp16(sK + (r * LQ + d0) * 2, qkv + base + (size_t)r * 1536 + 512 + h * 64 + d0);
    }
    #pragma unroll
    for (int it = 0, c = tid; it < 2; it++, c += 256)
        cp4(sM + c * 4, &mbits[((size_t)b * N_ + q0 + (c >> 2)) * 32 + (c & 3)]);
    cpcommit();

    float Oa[8][4];
    #pragma unroll
    for (int i = 0; i < 8; i++)
        #pragma unroll
        for (int j = 0; j < 4; j++) Oa[i][j] = 0.0f;
    float mrow0 = NINF, mrow1 = NINF, lrow0 = 0.0f, lrow1 = 0.0f;

    int aRow = w * 16 + ((lane >> 3) & 1) * 8 + (lane & 7);
    int aSel = (lane >> 4) * 8;
    int bRowOff = (lane >> 4) * 8 + (lane & 7);
    int bSel = ((lane >> 3) & 1) * 8;
    int vKeyOff = ((lane >> 3) & 1) * 8 + (lane & 7);
    int vDSel = (lane >> 4);

    cpwait0();
    __syncthreads();

    for (int kt = 0; kt < 8; kt++) {
        int cur = kt & 1;
        // issue V[kt] (overlaps S compute)
        #pragma unroll
        for (int it = 0, c = tid; it < 4; it++, c += 256) {
            int r = c >> 3, d0 = (c & 7) * 8;
            cp16(sV + (r * LQ + d0) * 2,
                 qkv + base + (size_t)(kt * 128 + r) * 1536 + 1024 + h * 64 + d0);
        }
        cpcommit();

        // S = Q K^T from Ks
        float sacc[16][4];
        #pragma unroll
        for (int nf = 0; nf < 16; nf++)
            #pragma unroll
            for (int j = 0; j < 4; j++) sacc[nf][j] = 0.0f;
        #pragma unroll
        for (int kk = 0; kk < 64; kk += 16) {
            uint32_t aq[4];
            ldsm4(aq, sQ + (uint32_t)(aRow * LQ + kk + aSel) * 2);
            #pragma unroll
            for (int nfp = 0; nfp < 8; nfp++) {
                uint32_t bq[4];
                ldsm4(bq, sK + (uint32_t)((nfp * 16 + bRowOff) * LQ + kk + bSel) * 2);
                mma16816(sacc[2 * nfp], aq, bq[0], bq[1]);
                mma16816(sacc[2 * nfp + 1], aq, bq[2], bq[3]);
            }
        }

        // mask + scale + online softmax
        int r0l = w * 16 + g;
        uint32_t mwa[4], mwb[4];
        #pragma unroll
        for (int i = 0; i < 4; i++) {
            mwa[i] = mw[cur * 512 + r0l * 4 + i];
            mwb[i] = mw[cur * 512 + (r0l + 8) * 4 + i];
        }
        float mx0 = -3e38f, mx1 = -3e38f;
        #pragma unroll
        for (int nf = 0; nf < 16; nf++) {
            int c0 = nf * 8 + 2 * tg;
            uint32_t wa = mwa[c0 >> 5], wb = mwb[c0 >> 5];
            int shm = c0 & 31;
            float s00 = ((wa >> shm) & 1) ? NEGBIG : sacc[nf][0] * 0.125f;
            float s01 = ((wa >> (shm + 1)) & 1) ? NEGBIG : sacc[nf][1] * 0.125f;
            float s10 = ((wb >> shm) & 1) ? NEGBIG : sacc[nf][2] * 0.125f;
            float s11 = ((wb >> (shm + 1)) & 1) ? NEGBIG : sacc[nf][3] * 0.125f;
            sacc[nf][0] = s00; sacc[nf][1] = s01; sacc[nf][2] = s10; sacc[nf][3] = s11;
            mx0 = fmaxf(mx0, fmaxf(s00, s01));
            mx1 = fmaxf(mx1, fmaxf(s10, s11));
        }
        mx0 = fmaxf(mx0, __shfl_xor_sync(0xffffffffu, mx0, 1));
        mx0 = fmaxf(mx0, __shfl_xor_sync(0xffffffffu, mx0, 2));
        mx1 = fmaxf(mx1, __shfl_xor_sync(0xffffffffu, mx1, 1));
        mx1 = fmaxf(mx1, __shfl_xor_sync(0xffffffffu, mx1, 2));
        float mn0 = fmaxf(mrow0, mx0), mn1 = fmaxf(mrow1, mx1);
        float cf0 = __expf(mrow0 - mn0), cf1 = __expf(mrow1 - mn1);
        mrow0 = mn0; mrow1 = mn1;
        float rs0 = 0.0f, rs1 = 0.0f;
        #pragma unroll
        for (int nf = 0; nf < 16; nf++) {
            float p00 = __expf(sacc[nf][0] - mn0);
            float p01 = __expf(sacc[nf][1] - mn0);
            float p10 = __expf(sacc[nf][2] - mn1);
            float p11 = __expf(sacc[nf][3] - mn1);
            sacc[nf][0] = p00; sacc[nf][1] = p01; sacc[nf][2] = p10; sacc[nf][3] = p11;
            rs0 += p00 + p01; rs1 += p10 + p11;
        }
        rs0 += __shfl_xor_sync(0xffffffffu, rs0, 1);
        rs0 += __shfl_xor_sync(0xffffffffu, rs0, 2);
        rs1 += __shfl_xor_sync(0xffffffffu, rs1, 1);
        rs1 += __shfl_xor_sync(0xffffffffu, rs1, 2);
        lrow0 = lrow0 * cf0 + rs0;
        lrow1 = lrow1 * cf1 + rs1;
        #pragma unroll
        for (int df = 0; df < 8; df++) {
            Oa[df][0] *= cf0; Oa[df][1] *= cf0;
            Oa[df][2] *= cf1; Oa[df][3] *= cf1;
        }
        uint32_t pa[8][4];
        #pragma unroll
        for (int f = 0; f < 8; f++) {
            pa[f][0] = packbf(sacc[2 * f][0], sacc[2 * f][1]);
            pa[f][1] = packbf(sacc[2 * f][2], sacc[2 * f][3]);
            pa[f][2] = packbf(sacc[2 * f + 1][0], sacc[2 * f + 1][1]);
            pa[f][3] = packbf(sacc[2 * f + 1][2], sacc[2 * f + 1][3]);
        }
        __syncthreads();            // all warps done with Ks

        bool more = kt < 7;
        if (more) {                 // issue K[kt+1] + mask[kt+1] (overlaps PV)
            #pragma unroll
            for (int it = 0, c = tid; it < 4; it++, c += 256) {
                int r = c >> 3, d0 = (c & 7) * 8;
                cp16(sK + (r * LQ + d0) * 2,
                     qkv + base + (size_t)((kt + 1) * 128 + r) * 1536 + 512 + h * 64 + d0);
            }
            #pragma unroll
            for (int it = 0, c = tid; it < 2; it++, c += 256)
                cp4(sM + ((cur ^ 1) * 512 + c) * 4,
                    &mbits[((size_t)b * N_ + q0 + (c >> 2)) * 32 + (kt + 1) * 4 + (c & 3)]);
            cpcommit();
            cpwait1();              // V arrived (K still in flight)
        } else {
            cpwait0();
        }
        __syncthreads();

        // O += P V
        #pragma unroll
        for (int f = 0; f < 8; f++) {
            #pragma unroll
            for (int q = 0; q < 4; q++) {
                uint32_t bv[4];
                ldsm4t(bv, sV + (uint32_t)((f * 16 + vKeyOff) * LQ + (vDSel + 2 * q) * 8) * 2);
                mma16816(Oa[2 * q], pa[f], bv[0], bv[1]);
                mma16816(Oa[2 * q + 1], pa[f], bv[2], bv[3]);
            }
        }
        cpwait0();                  // K[kt+1] arrived
        __syncthreads();            // Vs free for next issue; mw visible
    }

    float inv0 = 1.0f / lrow0, inv1 = 1.0f / lrow1;
    int orow = b * N_ + q0 + w * 16 + g;
    #pragma unroll
    for (int df = 0; df < 8; df++) {
        int col = h * 64 + df * 8 + 2 * tg;
        *(__nv_bfloat162*)(attn + (size_t)orow * 512 + col) =
            __floats2bfloat162_rn(Oa[df][0] * inv0, Oa[df][1] * inv0);
        *(__nv_bfloat162*)(attn + (size_t)(orow + 8) * 512 + col) =
            __floats2bfloat162_rn(Oa[df][2] * inv1, Oa[df][3] * inv1);
    }
}

// ---------------- att_topk from softmax row 0 ----------------
__device__ __forceinline__ float blkmax(float v, float* red, int tid) {
    #pragma unroll
    for (int o = 16; o > 0; o >>= 1) v = fmaxf(v, __shfl_xor_sync(0xffffffffu, v, o));
    if ((tid & 31) == 0) red[tid >> 5] = v;
    __syncthreads();
    if (tid < 32) {
        float t = red[tid];
        #pragma unroll
        for (int o = 16; o > 0; o >>= 1) t = fmaxf(t, __shfl_xor_sync(0xffffffffu, t, o));
        if (tid == 0) red[0] = t;
    }
    __syncthreads();
    float r = red[0];
    __syncthreads();
    return r;
}
__device__ __forceinline__ float blksum(float v, float* red, int tid) {
    #pragma unroll
    for (int o = 16; o > 0; o >>= 1) v += __shfl_xor_sync(0xffffffffu, v, o);
    if ((tid & 31) == 0) red[tid >> 5] = v;
    __syncthreads();
    if (tid < 32) {
        float t = red[tid];
        #pragma unroll
        for (int o = 16; o > 0; o >>= 1) t += __shfl_xor_sync(0xffffffffu, t, o);
        if (tid == 0) red[0] = t;
    }
    __syncthreads();
    float r = red[0];
    __syncthreads();
    return r;
}
__global__ void __launch_bounds__(1024) topk0_kernel(const bf16* __restrict__ qkv,
                                                     const float* __restrict__ mask,
                                                     float* __restrict__ topk) {
    int b = blockIdx.x, m = threadIdx.x;
    __shared__ float q0s[512];
    __shared__ float red[32];
    size_t rb = (size_t)b * N_ * 1536;
    if (m < 512) q0s[m] = __bfloat162float(qkv[rb + m]);
    __syncthreads();
    const bf16* krow = qkv + rb + (size_t)m * 1536 + 512;
    float s[8];
    #pragma unroll
    for (int h = 0; h < 8; h++) {
        float acc = 0.0f;
        #pragma unroll
        for (int j = 0; j < 64; j += 8) {
            uint4 kv = *(const uint4*)(krow + h * 64 + j);
            bf16 t[8]; *(uint4*)t = kv;
            #pragma unroll
            for (int i = 0; i < 8; i++) acc += q0s[h * 64 + j + i] * __bfloat162float(t[i]);
        }
        s[h] = acc * 0.125f;
    }
    if (mask[(size_t)b * N_ * N_ + m] == 1.0f)
        #pragma unroll
        for (int h = 0; h < 8; h++) s[h] = NEGBIG;
    float out = 0.0f;
    #pragma unroll
    for (int h = 0; h < 8; h++) {
        float M = blkmax(s[h], red, m);
        float p = __expf(s[h] - M);
        float L = blksum(p, red, m);
        out += p / L;
    }
    topk[b * N_ + m] = out * 0.125f;
}

__global__ void __launch_bounds__(1024) prune_kernel(const float* __restrict__ topk,
                                                     float* __restrict__ out) {
    int b = blockIdx.x, m = threadIdx.x;
    __shared__ float key[N_];
    float km = (m == 0) ? NINF : topk[b * N_ + m];
    key[m] = km;
    __syncthreads();
    int rank = 0;
    for (int j = 0; j < N_; j++) {
        float kj = key[j];
        rank += (kj > km) || (kj == km && j < m);
    }
    if (rank >= 959 && rank < 1023) out[4194304 + b * 64 + (rank - 959)] = (float)m;
    if (m == 0) out[4194816 + b] = -1.0f;
    if (m < 16) out[4194824 + b * 16 + m] = 0.0f;
}

// ---------------- bf16 GEMM, cp.async 2-stage. EPI: 0=bf16, 2=+bias+resid ------
template<int EPI>
__global__ void __launch_bounds__(256) gemm_k(
    const bf16* __restrict__ A, const bf16* __restrict__ Bm, void* __restrict__ Cp,
    int K, int lda, int ldb, int ldc,
    const float* __restrict__ bias, const float* __restrict__ resid)
{
    constexpr int LA = 40, LB = 136;
    __shared__ bf16 As[2][128 * LA];
    __shared__ bf16 Bs[2][32 * LB];
    int tid = threadIdx.x, warp = tid >> 5, lane = tid & 31;
    int g = lane >> 2, tg = lane & 3;
    int warpM = warp & 3, warpN = warp >> 2;
    int row0 = blockIdx.y * 128, col0 = blockIdx.x * 128;
    uint32_t sA = (uint32_t)__cvta_generic_to_shared(As);
    uint32_t sB = (uint32_t)__cvta_generic_to_shared(Bs);
    int koff = ((lane >> 3) & 1) * 8 + (lane & 7);
    int nsel = (lane >> 4) * 8;

    float acc[2][8][4];
    #pragma unroll
    for (int a = 0; a < 2; a++)
        #pragma unroll
        for (int b2 = 0; b2 < 8; b2++)
            #pragma unroll
            for (int c = 0; c < 4; c++) acc[a][b2][c] = 0.0f;

    auto issue = [&](int st, int k0) {
        #pragma unroll
        for (int it = 0, c = tid; it < 2; it++, c += 256) {
            int r = c >> 2, kc = (c & 3) * 8;
            cp16(sA + (st * 128 * LA + r * LA + kc) * 2,
                 A + (size_t)(row0 + r) * lda + k0 + kc);
        }
        #pragma unroll
        for (int it = 0, c = tid; it < 2; it++, c += 256) {
            int kk = c >> 4, nc = (c & 15) * 8;
            cp16(sB + (st * 32 * LB + kk * LB + nc) * 2,
                 Bm + (size_t)(k0 + kk) * ldb + col0 + nc);
        }
        cpcommit();
    };

    issue(0, 0);
    int nk = K / 32;
    for (int i = 0; i < nk; i++) {
        int st = i & 1;
        cpwait0();
        __syncthreads();
        if (i + 1 < nk) issue(st ^ 1, (i + 1) * 32);
        const bf16* Ab = As[st];
        uint32_t sBst = sB + st * 32 * LB * 2;
        #pragma unroll
        for (int kk = 0; kk < 32; kk += 16) {
            uint32_t af[2][4];
            #pragma unroll
            for (int mt = 0; mt < 2; mt++) {
                const bf16* p = &Ab[(warpM * 32 + mt * 16 + g) * LA + kk + 2 * tg];
                af[mt][0] = *(const uint32_t*)p;
                af[mt][1] = *(const uint32_t*)(p + 8 * LA);
                af[mt][2] = *(const uint32_t*)(p + 8);
                af[mt][3] = *(const uint32_t*)(p + 8 * LA + 8);
            }
            #pragma unroll
            for (int p2 = 0; p2 < 4; p2++) {
                uint32_t bq[4];
                ldsm4t(bq, sBst + (uint32_t)((kk + koff) * LB + warpN * 64 + p2 * 16 + nsel) * 2);
                #pragma unroll
                for (int mt = 0; mt < 2; mt++) {
                    mma16816(acc[mt][2 * p2], af[mt], bq[0], bq[1]);
                    mma16816(acc[mt][2 * p2 + 1], af[mt], bq[2], bq[3]);
                }
            }
        }
        __syncthreads();
    }
    #pragma unroll
    for (int mt = 0; mt < 2; mt++)
        #pragma unroll
        for (int nt = 0; nt < 8; nt++) {
            int r = row0 + warpM * 32 + mt * 16 + g;
            int cc = col0 + warpN * 64 + nt * 8 + 2 * tg;
            #pragma unroll
            for (int hf = 0; hf < 2; hf++) {
                int rr = r + hf * 8;
                float v0 = acc[mt][nt][hf * 2], v1 = acc[mt][nt][hf * 2 + 1];
                long idx = (long)rr * ldc + cc;
                if (EPI == 0) {
                    *(__nv_bfloat162*)((bf16*)Cp + idx) = __floats2bfloat162_rn(v0, v1);
                } else {
                    v0 += bias[cc] + resid[idx];
                    v1 += bias[cc + 1] + resid[idx + 1];
                    *(float2*)((float*)Cp + idx) = make_float2(v0, v1);
                }
            }
        }
}

// ---------------- tf32 GEMM, cp.async 2-stage, dynamic smem ----------------
#define TF_SMEM ((2 * 128 * 40 + 2 * 32 * 136) * 4)   // 75776
template<int EPI>
__global__ void __launch_bounds__(256) gemm_tf32(
    const float* __restrict__ A, const float* __restrict__ Bm, float* __restrict__ C,
    int K, int lda, int ldb, int ldc,
    const float* __restrict__ bias, const float* __restrict__ resid)
{
    constexpr int LA = 40, LB = 136;
    extern __shared__ float smf[];
    float* Asf = smf;
    float* Bsf = smf + 2 * 128 * LA;
    int tid = threadIdx.x, warp = tid >> 5, lane = tid & 31;
    int g = lane >> 2, tg = lane & 3;
    int warpM = warp & 3, warpN = warp >> 2;
    int row0 = blockIdx.y * 128, col0 = blockIdx.x * 128;
    uint32_t sA = (uint32_t)__cvta_generic_to_shared(Asf);
    uint32_t sB = (uint32_t)__cvta_generic_to_shared(Bsf);

    float acc[2][8][4];
    #pragma unroll
    for (int a = 0; a < 2; a++)
        #pragma unroll
        for (int b2 = 0; b2 < 8; b2++)
            #pragma unroll
            for (int c = 0; c < 4; c++) acc[a][b2][c] = 0.0f;

    auto issue = [&](int st, int k0) {
        #pragma unroll
        for (int it = 0, c = tid; it < 4; it++, c += 256) {
            int r = c >> 3, kc = (c & 7) * 4;
            cp16(sA + (st * 128 * LA + r * LA + kc) * 4,
                 A + (size_t)(row0 + r) * lda + k0 + kc);
        }
        #pragma unroll
        for (int it = 0, c = tid; it < 4; it++, c += 256) {
            int kk = c >> 5, nc = (c & 31) * 4;
            cp16(sB + (st * 32 * LB + kk * LB + nc) * 4,
                 Bm + (size_t)(k0 + kk) * ldb + col0 + nc);
        }
        cpcommit();
    };

    issue(0, 0);
    int nk = K / 32;
    for (int i = 0; i < nk; i++) {
        int st = i & 1;
        cpwait0();
        __syncthreads();
        if (i + 1 < nk) issue(st ^ 1, (i + 1) * 32);
        const float* Ab = Asf + st * 128 * LA;
        const float* Bb = Bsf + st * 32 * LB;
        #pragma unroll
        for (int kk = 0; kk < 32; kk += 8) {
            uint32_t af[2][4], bfr[8][2];
            #pragma unroll
            for (int mt = 0; mt < 2; mt++) {
                int rb = warpM * 32 + mt * 16 + g;
                af[mt][0] = *(const uint32_t*)&Ab[rb * LA + kk + tg];
                af[mt][1] = *(const uint32_t*)&Ab[(rb + 8) * LA + kk + tg];
                af[mt][2] = *(const uint32_t*)&Ab[rb * LA + kk + tg + 4];
                af[mt][3] = *(const uint32_t*)&Ab[(rb + 8) * LA + kk + tg + 4];
            }
            #pragma unroll
            for (int nt = 0; nt < 8; nt++) {
                int nb = warpN * 64 + nt * 8 + g;
                bfr[nt][0] = *(const uint32_t*)&Bb[(kk + tg) * LB + nb];
                bfr[nt][1] = *(const uint32_t*)&Bb[(kk + tg + 4) * LB + nb];
            }
            #pragma unroll
            for (int mt = 0; mt < 2; mt++)
                #pragma unroll
                for (int nt = 0; nt < 8; nt++)
                    mma1688t(acc[mt][nt], af[mt], bfr[nt][0], bfr[nt][1]);
        }
        __syncthreads();
    }
    #pragma unroll
    for (int mt = 0; mt < 2; mt++)
        #pragma unroll
        for (int nt = 0; nt < 8; nt++) {
            int r = row0 + warpM * 32 + mt * 16 + g;
            int cc = col0 + warpN * 64 + nt * 8 + 2 * tg;
            #pragma unroll
            for (int hf = 0; hf < 2; hf++) {
                int rr = r + hf * 8;
                float v0 = acc[mt][nt][hf * 2], v1 = acc[mt][nt][hf * 2 + 1];
                long idx = (long)rr * ldc + cc;
                if (EPI == 2) {
                    v0 += bias[cc] + resid[idx];
                    v1 += bias[cc + 1] + resid[idx + 1];
                } else {
                    v0 += bias[cc]; v1 += bias[cc + 1];
                    v0 = 0.5f * v0 * (1.0f + erff(v0 * 0.70710678f));
                    v1 = 0.5f * v1 * (1.0f + erff(v1 * 0.70710678f));
                }
                *(float2*)(C + idx) = make_float2(v0, v1);
            }
        }
}

// ---------------- host ----------------
template <typename T>
static T* symaddr(const T& sym) {
    void* p = nullptr;
    cudaGetSymbolAddress(&p, sym);
    return (T*)p;
}

extern "C" void kernel_launch(void* const* d_in, const int* in_sizes, int n_in,
                              void* d_out, int out_size) {
    const float* x    = (const float*)d_in[0];
    const float* mask = (const float*)d_in[1];
    const float* Wqkv = (const float*)d_in[2];
    const float* Wout = (const float*)d_in[3];
    const float* bout = (const float*)d_in[4];
    const float* ln1g = (const float*)d_in[5];
    const float* ln1b = (const float*)d_in[6];
    const float* ln2g = (const float*)d_in[7];
    const float* ln2b = (const float*)d_in[8];
    const float* W1   = (const float*)d_in[9];
    const float* b1   = (const float*)d_in[10];
    const float* W2   = (const float*)d_in[11];
    const float* b2   = (const float*)d_in[12];

    bf16* h = (bf16*)symaddr(g_h);
    bf16* qkv = (bf16*)symaddr(g_qkv);
    bf16* attn = (bf16*)symaddr(g_attn);
    float* x1 = (float*)symaddr(g_x1);
    float* h2f = (float*)symaddr(g_h2f);
    float* fff = (float*)symaddr(g_fff);
    float* tk = (float*)symaddr(g_topk);
    uint32_t* mb = (uint32_t*)symaddr(g_mbits);
    bf16* wqkv = (bf16*)symaddr(g_Wqkv);
    bf16* wout = (bf16*)symaddr(g_Wout);

    cudaFuncSetAttribute(flash_kernel, cudaFuncAttributeMaxDynamicSharedMemorySize, FL_SMEM);
    cudaFuncSetAttribute(gemm_tf32<2>, cudaFuncAttributeMaxDynamicSharedMemorySize, TF_SMEM);
    cudaFuncSetAttribute(gemm_tf32<3>, cudaFuncAttributeMaxDynamicSharedMemorySize, TF_SMEM);

    cvt_kernel<<<(D_ * 3 * D_ + 255) / 256, 256>>>(Wqkv, wqkv, D_ * 3 * D_);
    cvt_kernel<<<(D_ * D_ + 255) / 256, 256>>>(Wout, wout, D_ * D_);
    maskbits_kernel<<<B_ * N_ * N_ / 256, 256>>>(mask, mb);
    ln_kernel<true><<<ROWS_, 128>>>(x, ln1g, ln1b, h);

    gemm_k<0><<<dim3(12, 64), 256>>>(h, wqkv, qkv, D_, D_, 3 * D_, 3 * D_, nullptr, nullptr);
    flash_kernel<<<dim3(8, 64), 256, FL_SMEM>>>(qkv, mb, attn);
    topk0_kernel<<<B_, 1024>>>(qkv, mask, tk);
    prune_kernel<<<B_, 1024>>>(tk, (float*)d_out);
    gemm_k<2><<<dim3(4, 64), 256>>>(attn, wout, x1, D_, D_, D_, D_, bout, x);
    ln_kernel<false><<<ROWS_, 128>>>(x1, ln2g, ln2b, h2f);
    gemm_tf32<3><<<dim3(16, 64), 256, TF_SMEM>>>(h2f, W1, fff, D_, D_, MLP_, MLP_, b1, nullptr);
    gemm_tf32<2><<<dim3(4, 64), 256, TF_SMEM>>>(fff, W2, (float*)d_out, MLP_, MLP_, D_, D_, b2, x1);
}

// round 6
// speedup vs baseline: 2.3162x; 1.2043x over previous
#include <cuda_runtime.h>
#include <cuda_bf16.h>
#include <cuda_fp16.h>
#include <cstdint>

using bf16 = __nv_bfloat16;

#define B_ 8
#define N_ 1024
#define D_ 512
#define MLP_ 2048
#define ROWS_ (B_ * N_)
#define NEGBIG (-1e10f)
#define NINF __int_as_float(0xff800000)

// ---------------- scratch ----------------
__device__ bf16  g_h[ROWS_ * D_];
__device__ bf16  g_qkv[ROWS_ * 3 * D_];
__device__ bf16  g_attn[ROWS_ * D_];
__device__ float g_x1[ROWS_ * D_];
__device__ __half g_h2h[ROWS_ * D_];
__device__ __half g_ffh[ROWS_ * MLP_];
__device__ float g_topk[B_ * N_];
__device__ uint32_t g_mbits[B_ * N_ * 32];
__device__ bf16  g_Wqkv[D_ * 3 * D_];
__device__ bf16  g_Wout[D_ * D_];
__device__ __half g_W1h[D_ * MLP_];
__device__ __half g_W2h[MLP_ * D_];

// ---------------- helpers ----------------
template<bool HALF>
__device__ __forceinline__ void mma16816(float* c, const uint32_t* a, uint32_t b0, uint32_t b1) {
    if (HALF)
        asm volatile("mma.sync.aligned.m16n8k16.row.col.f32.f16.f16.f32 "
                     "{%0,%1,%2,%3},{%4,%5,%6,%7},{%8,%9},{%0,%1,%2,%3};\n"
                     : "+f"(c[0]), "+f"(c[1]), "+f"(c[2]), "+f"(c[3])
                     : "r"(a[0]), "r"(a[1]), "r"(a[2]), "r"(a[3]), "r"(b0), "r"(b1));
    else
        asm volatile("mma.sync.aligned.m16n8k16.row.col.f32.bf16.bf16.f32 "
                     "{%0,%1,%2,%3},{%4,%5,%6,%7},{%8,%9},{%0,%1,%2,%3};\n"
                     : "+f"(c[0]), "+f"(c[1]), "+f"(c[2]), "+f"(c[3])
                     : "r"(a[0]), "r"(a[1]), "r"(a[2]), "r"(a[3]), "r"(b0), "r"(b1));
}
__device__ __forceinline__ void ldsm4(uint32_t* r, uint32_t a) {
    asm volatile("ldmatrix.sync.aligned.m8n8.x4.shared.b16 {%0,%1,%2,%3},[%4];"
                 : "=r"(r[0]), "=r"(r[1]), "=r"(r[2]), "=r"(r[3]) : "r"(a));
}
__device__ __forceinline__ void ldsm4t(uint32_t* r, uint32_t a) {
    asm volatile("ldmatrix.sync.aligned.m8n8.x4.trans.shared.b16 {%0,%1,%2,%3},[%4];"
                 : "=r"(r[0]), "=r"(r[1]), "=r"(r[2]), "=r"(r[3]) : "r"(a));
}
__device__ __forceinline__ uint32_t packbf(float x, float y) {
    __nv_bfloat162 t = __floats2bfloat162_rn(x, y);
    return *(uint32_t*)&t;
}
__device__ __forceinline__ void cp16(uint32_t s, const void* g) {
    asm volatile("cp.async.cg.shared.global [%0],[%1],16;\n" :: "r"(s), "l"(g));
}
__device__ __forceinline__ void cp4(uint32_t s, const void* g) {
    asm volatile("cp.async.ca.shared.global [%0],[%1],4;\n" :: "r"(s), "l"(g));
}
__device__ __forceinline__ void cpcommit() { asm volatile("cp.async.commit_group;\n"); }
__device__ __forceinline__ void cpwait0() { asm volatile("cp.async.wait_group 0;\n"); }
__device__ __forceinline__ void cpwait1() { asm volatile("cp.async.wait_group 1;\n"); }

__global__ void cvt_kernel(const float* __restrict__ s, bf16* __restrict__ d, int n) {
    int i = blockIdx.x * blockDim.x + threadIdx.x;
    if (i < n) d[i] = __float2bfloat16(s[i]);
}
__global__ void cvth_kernel(const float* __restrict__ s, __half* __restrict__ d, int n) {
    int i = blockIdx.x * blockDim.x + threadIdx.x;
    if (i < n) d[i] = __float2half_rn(s[i]);
}

__global__ void maskbits_kernel(const float* __restrict__ mask, uint32_t* __restrict__ bits) {
    int idx = blockIdx.x * blockDim.x + threadIdx.x;
    uint32_t bal = __ballot_sync(0xffffffffu, mask[idx] == 1.0f);
    if ((idx & 31) == 0) bits[idx >> 5] = bal;
}

// ---------------- LayerNorm. OUT: 0=bf16, 1=fp16 ----------------
template<int OUT>
__global__ void __launch_bounds__(128) ln_kernel(const float* __restrict__ x,
                                                 const float* __restrict__ gam,
                                                 const float* __restrict__ bet,
                                                 void* __restrict__ out) {
    int row = blockIdx.x, t = threadIdx.x;
    float4 a = ((const float4*)(x + (size_t)row * D_))[t];
    float s = a.x + a.y + a.z + a.w;
    float sq = a.x * a.x + a.y * a.y + a.z * a.z + a.w * a.w;
    __shared__ float sh[8];
    #pragma unroll
    for (int o = 16; o > 0; o >>= 1) {
        s += __shfl_down_sync(0xffffffffu, s, o);
        sq += __shfl_down_sync(0xffffffffu, sq, o);
    }
    int w = t >> 5;
    if ((t & 31) == 0) { sh[w] = s; sh[4 + w] = sq; }
    __syncthreads();
    if (t == 0) {
        float S = sh[0] + sh[1] + sh[2] + sh[3];
        float Q = sh[4] + sh[5] + sh[6] + sh[7];
        float mu = S * (1.0f / D_);
        sh[0] = mu; sh[1] = rsqrtf(Q * (1.0f / D_) - mu * mu + 1e-5f);
    }
    __syncthreads();
    float mu = sh[0], rs = sh[1];
    float4 gv = ((const float4*)gam)[t];
    float4 bv = ((const float4*)bet)[t];
    float o0 = (a.x - mu) * rs * gv.x + bv.x;
    float o1 = (a.y - mu) * rs * gv.y + bv.y;
    float o2 = (a.z - mu) * rs * gv.z + bv.z;
    float o3 = (a.w - mu) * rs * gv.w + bv.w;
    if (OUT == 0) {
        bf16* o = (bf16*)out + (size_t)row * D_ + t * 4;
        ((__nv_bfloat162*)o)[0] = __floats2bfloat162_rn(o0, o1);
        ((__nv_bfloat162*)o)[1] = __floats2bfloat162_rn(o2, o3);
    } else {
        __half* o = (__half*)out + (size_t)row * D_ + t * 4;
        ((__half2*)o)[0] = __floats2half2_rn(o0, o1);
        ((__half2*)o)[1] = __floats2half2_rn(o2, o3);
    }
}

// ---------------- flash attention, cp.async pipelined ----------------
#define LQ 72
#define FL_SMEM (3 * 128 * LQ * 2 + 2 * 512 * 4)   // 59392
__global__ void __launch_bounds__(256) flash_kernel(const bf16* __restrict__ qkv,
                                                    const uint32_t* __restrict__ mbits,
                                                    bf16* __restrict__ attn) {
    extern __shared__ char sm[];
    uint32_t sQ = (uint32_t)__cvta_generic_to_shared(sm);
    uint32_t sK = sQ + 128 * LQ * 2;
    uint32_t sV = sK + 128 * LQ * 2;
    uint32_t sM = sV + 128 * LQ * 2;
    uint32_t* mw = (uint32_t*)(sm + 3 * 128 * LQ * 2);

    int bh = blockIdx.y, b = bh >> 3, h = bh & 7;
    int tid = threadIdx.x, w = tid >> 5, lane = tid & 31, g = lane >> 2, tg = lane & 3;
    int q0 = blockIdx.x * 128;
    size_t base = (size_t)b * N_ * 1536;

    #pragma unroll
    for (int it = 0, c = tid; it < 4; it++, c += 256) {
        int r = c >> 3, d0 = (c & 7) * 8;
        cp16(sQ + (r * LQ + d0) * 2, qkv + base + (size_t)(q0 + r) * 1536 + h * 64 + d0);
        cp16(sK + (r * LQ + d0) * 2, qkv + base + (size_t)r * 1536 + 512 + h * 64 + d0);
    }
    #pragma unroll
    for (int it = 0, c = tid; it < 2; it++, c += 256)
        cp4(sM + c * 4, &mbits[((size_t)b * N_ + q0 + (c >> 2)) * 32 + (c & 3)]);
    cpcommit();

    float Oa[8][4];
    #pragma unroll
    for (int i = 0; i < 8; i++)
        #pragma unroll
        for (int j = 0; j < 4; j++) Oa[i][j] = 0.0f;
    float mrow0 = NINF, mrow1 = NINF, lrow0 = 0.0f, lrow1 = 0.0f;

    int aRow = w * 16 + ((lane >> 3) & 1) * 8 + (lane & 7);
    int aSel = (lane >> 4) * 8;
    int bRowOff = (lane >> 4) * 8 + (lane & 7);
    int bSel = ((lane >> 3) & 1) * 8;
    int vKeyOff = ((lane >> 3) & 1) * 8 + (lane & 7);
    int vDSel = (lane >> 4);

    cpwait0();
    __syncthreads();

    for (int kt = 0; kt < 8; kt++) {
        int cur = kt & 1;
        #pragma unroll
        for (int it = 0, c = tid; it < 4; it++, c += 256) {
            int r = c >> 3, d0 = (c & 7) * 8;
            cp16(sV + (r * LQ + d0) * 2,
                 qkv + base + (size_t)(kt * 128 + r) * 1536 + 1024 + h * 64 + d0);
        }
        cpcommit();

        float sacc[16][4];
        #pragma unroll
        for (int nf = 0; nf < 16; nf++)
            #pragma unroll
            for (int j = 0; j < 4; j++) sacc[nf][j] = 0.0f;
        #pragma unroll
        for (int kk = 0; kk < 64; kk += 16) {
            uint32_t aq[4];
            ldsm4(aq, sQ + (uint32_t)(aRow * LQ + kk + aSel) * 2);
            #pragma unroll
            for (int nfp = 0; nfp < 8; nfp++) {
                uint32_t bq[4];
                ldsm4(bq, sK + (uint32_t)((nfp * 16 + bRowOff) * LQ + kk + bSel) * 2);
                mma16816<false>(sacc[2 * nfp], aq, bq[0], bq[1]);
                mma16816<false>(sacc[2 * nfp + 1], aq, bq[2], bq[3]);
            }
        }

        int r0l = w * 16 + g;
        uint32_t mwa[4], mwb[4];
        #pragma unroll
        for (int i = 0; i < 4; i++) {
            mwa[i] = mw[cur * 512 + r0l * 4 + i];
            mwb[i] = mw[cur * 512 + (r0l + 8) * 4 + i];
        }
        float mx0 = -3e38f, mx1 = -3e38f;
        #pragma unroll
        for (int nf = 0; nf < 16; nf++) {
            int c0 = nf * 8 + 2 * tg;
            uint32_t wa = mwa[c0 >> 5], wb = mwb[c0 >> 5];
            int shm = c0 & 31;
            float s00 = ((wa >> shm) & 1) ? NEGBIG : sacc[nf][0] * 0.125f;
            float s01 = ((wa >> (shm + 1)) & 1) ? NEGBIG : sacc[nf][1] * 0.125f;
            float s10 = ((wb >> shm) & 1) ? NEGBIG : sacc[nf][2] * 0.125f;
            float s11 = ((wb >> (shm + 1)) & 1) ? NEGBIG : sacc[nf][3] * 0.125f;
            sacc[nf][0] = s00; sacc[nf][1] = s01; sacc[nf][2] = s10; sacc[nf][3] = s11;
            mx0 = fmaxf(mx0, fmaxf(s00, s01));
            mx1 = fmaxf(mx1, fmaxf(s10, s11));
        }
        mx0 = fmaxf(mx0, __shfl_xor_sync(0xffffffffu, mx0, 1));
        mx0 = fmaxf(mx0, __shfl_xor_sync(0xffffffffu, mx0, 2));
        mx1 = fmaxf(mx1, __shfl_xor_sync(0xffffffffu, mx1, 1));
        mx1 = fmaxf(mx1, __shfl_xor_sync(0xffffffffu, mx1, 2));
        float mn0 = fmaxf(mrow0, mx0), mn1 = fmaxf(mrow1, mx1);
        float cf0 = __expf(mrow0 - mn0), cf1 = __expf(mrow1 - mn1);
        mrow0 = mn0; mrow1 = mn1;
        float rs0 = 0.0f, rs1 = 0.0f;
        #pragma unroll
        for (int nf = 0; nf < 16; nf++) {
            float p00 = __expf(sacc[nf][0] - mn0);
            float p01 = __expf(sacc[nf][1] - mn0);
            float p10 = __expf(sacc[nf][2] - mn1);
            float p11 = __expf(sacc[nf][3] - mn1);
            sacc[nf][0] = p00; sacc[nf][1] = p01; sacc[nf][2] = p10; sacc[nf][3] = p11;
            rs0 += p00 + p01; rs1 += p10 + p11;
        }
        rs0 += __shfl_xor_sync(0xffffffffu, rs0, 1);
        rs0 += __shfl_xor_sync(0xffffffffu, rs0, 2);
        rs1 += __shfl_xor_sync(0xffffffffu, rs1, 1);
        rs1 += __shfl_xor_sync(0xffffffffu, rs1, 2);
        lrow0 = lrow0 * cf0 + rs0;
        lrow1 = lrow1 * cf1 + rs1;
        #pragma unroll
        for (int df = 0; df < 8; df++) {
            Oa[df][0] *= cf0; Oa[df][1] *= cf0;
            Oa[df][2] *= cf1; Oa[df][3] *= cf1;
        }
        uint32_t pa[8][4];
        #pragma unroll
        for (int f = 0; f < 8; f++) {
            pa[f][0] = packbf(sacc[2 * f][0], sacc[2 * f][1]);
            pa[f][1] = packbf(sacc[2 * f][2], sacc[2 * f][3]);
            pa[f][2] = packbf(sacc[2 * f + 1][0], sacc[2 * f + 1][1]);
            pa[f][3] = packbf(sacc[2 * f + 1][2], sacc[2 * f + 1][3]);
        }
        __syncthreads();

        bool more = kt < 7;
        if (more) {
            #pragma unroll
            for (int it = 0, c = tid; it < 4; it++, c += 256) {
                int r = c >> 3, d0 = (c & 7) * 8;
                cp16(sK + (r * LQ + d0) * 2,
                     qkv + base + (size_t)((kt + 1) * 128 + r) * 1536 + 512 + h * 64 + d0);
            }
            #pragma unroll
            for (int it = 0, c = tid; it < 2; it++, c += 256)
                cp4(sM + ((cur ^ 1) * 512 + c) * 4,
                    &mbits[((size_t)b * N_ + q0 + (c >> 2)) * 32 + (kt + 1) * 4 + (c & 3)]);
            cpcommit();
            cpwait1();
        } else {
            cpwait0();
        }
        __syncthreads();

        #pragma unroll
        for (int f = 0; f < 8; f++) {
            #pragma unroll
            for (int q = 0; q < 4; q++) {
                uint32_t bv[4];
                ldsm4t(bv, sV + (uint32_t)((f * 16 + vKeyOff) * LQ + (vDSel + 2 * q) * 8) * 2);
                mma16816<false>(Oa[2 * q], pa[f], bv[0], bv[1]);
                mma16816<false>(Oa[2 * q + 1], pa[f], bv[2], bv[3]);
            }
        }
        cpwait0();
        __syncthreads();
    }

    float inv0 = 1.0f / lrow0, inv1 = 1.0f / lrow1;
    int orow = b * N_ + q0 + w * 16 + g;
    #pragma unroll
    for (int df = 0; df < 8; df++) {
        int col = h * 64 + df * 8 + 2 * tg;
        *(__nv_bfloat162*)(attn + (size_t)orow * 512 + col) =
            __floats2bfloat162_rn(Oa[df][0] * inv0, Oa[df][1] * inv0);
        *(__nv_bfloat162*)(attn + (size_t)(orow + 8) * 512 + col) =
            __floats2bfloat162_rn(Oa[df][2] * inv1, Oa[df][3] * inv1);
    }
}

// ---------------- att_topk from softmax row 0 ----------------
__device__ __forceinline__ float blkmax(float v, float* red, int tid) {
    #pragma unroll
    for (int o = 16; o > 0; o >>= 1) v = fmaxf(v, __shfl_xor_sync(0xffffffffu, v, o));
    if ((tid & 31) == 0) red[tid >> 5] = v;
    __syncthreads();
    if (tid < 32) {
        float t = red[tid];
        #pragma unroll
        for (int o = 16; o > 0; o >>= 1) t = fmaxf(t, __shfl_xor_sync(0xffffffffu, t, o));
        if (tid == 0) red[0] = t;
    }
    __syncthreads();
    float r = red[0];
    __syncthreads();
    return r;
}
__device__ __forceinline__ float blksum(float v, float* red, int tid) {
    #pragma unroll
    for (int o = 16; o > 0; o >>= 1) v += __shfl_xor_sync(0xffffffffu, v, o);
    if ((tid & 31) == 0) red[tid >> 5] = v;
    __syncthreads();
    if (tid < 32) {
        float t = red[tid];
        #pragma unroll
        for (int o = 16; o > 0; o >>= 1) t += __shfl_xor_sync(0xffffffffu, t, o);
        if (tid == 0) red[0] = t;
    }
    __syncthreads();
    float r = red[0];
    __syncthreads();
    return r;
}
__global__ void __launch_bounds__(1024) topk0_kernel(const bf16* __restrict__ qkv,
                                                     const float* __restrict__ mask,
                                                     float* __restrict__ topk) {
    int b = blockIdx.x, m = threadIdx.x;
    __shared__ float q0s[512];
    __shared__ float red[32];
    size_t rb = (size_t)b * N_ * 1536;
    if (m < 512) q0s[m] = __bfloat162float(qkv[rb + m]);
    __syncthreads();
    const bf16* krow = qkv + rb + (size_t)m * 1536 + 512;
    float s[8];
    #pragma unroll
    for (int h = 0; h < 8; h++) {
        float acc = 0.0f;
        #pragma unroll
        for (int j = 0; j < 64; j += 8) {
            uint4 kv = *(const uint4*)(krow + h * 64 + j);
            bf16 t[8]; *(uint4*)t = kv;
            #pragma unroll
            for (int i = 0; i < 8; i++) acc += q0s[h * 64 + j + i] * __bfloat162float(t[i]);
        }
        s[h] = acc * 0.125f;
    }
    if (mask[(size_t)b * N_ * N_ + m] == 1.0f)
        #pragma unroll
        for (int h = 0; h < 8; h++) s[h] = NEGBIG;
    float out = 0.0f;
    #pragma unroll
    for (int h = 0; h < 8; h++) {
        float M = blkmax(s[h], red, m);
        float p = __expf(s[h] - M);
        float L = blksum(p, red, m);
        out += p / L;
    }
    topk[b * N_ + m] = out * 0.125f;
}

__global__ void __launch_bounds__(1024) prune_kernel(const float* __restrict__ topk,
                                                     float* __restrict__ out) {
    int b = blockIdx.x, m = threadIdx.x;
    __shared__ float key[N_];
    float km = (m == 0) ? NINF : topk[b * N_ + m];
    key[m] = km;
    __syncthreads();
    int rank = 0;
    for (int j = 0; j < N_; j++) {
        float kj = key[j];
        rank += (kj > km) || (kj == km && j < m);
    }
    if (rank >= 959 && rank < 1023) out[4194304 + b * 64 + (rank - 959)] = (float)m;
    if (m == 0) out[4194816 + b] = -1.0f;
    if (m < 16) out[4194824 + b * 16 + m] = 0.0f;
}

// ------- 16-bit GEMM, cp.async 2-stage. HALF: fp16 vs bf16 datapath.
// EPI: 0 = store 16-bit; 2 = +bias+resid -> fp32; 3 = gelu(.+bias) -> 16-bit
template<int EPI, bool HALF>
__global__ void __launch_bounds__(256) gemm_k(
    const uint16_t* __restrict__ A, const uint16_t* __restrict__ Bm, void* __restrict__ Cp,
    int K, int lda, int ldb, int ldc,
    const float* __restrict__ bias, const float* __restrict__ resid)
{
    constexpr int LA = 40, LB = 136;
    __shared__ uint16_t As[2][128 * LA];
    __shared__ uint16_t Bs[2][32 * LB];
    int tid = threadIdx.x, warp = tid >> 5, lane = tid & 31;
    int g = lane >> 2, tg = lane & 3;
    int warpM = warp & 3, warpN = warp >> 2;
    int row0 = blockIdx.y * 128, col0 = blockIdx.x * 128;
    uint32_t sA = (uint32_t)__cvta_generic_to_shared(As);
    uint32_t sB = (uint32_t)__cvta_generic_to_shared(Bs);
    int koff = ((lane >> 3) & 1) * 8 + (lane & 7);
    int nsel = (lane >> 4) * 8;

    float acc[2][8][4];
    #pragma unroll
    for (int a = 0; a < 2; a++)
        #pragma unroll
        for (int b2 = 0; b2 < 8; b2++)
            #pragma unroll
            for (int c = 0; c < 4; c++) acc[a][b2][c] = 0.0f;

    auto issue = [&](int st, int k0) {
        #pragma unroll
        for (int it = 0, c = tid; it < 2; it++, c += 256) {
            int r = c >> 2, kc = (c & 3) * 8;
            cp16(sA + (st * 128 * LA + r * LA + kc) * 2,
                 A + (size_t)(row0 + r) * lda + k0 + kc);
        }
        #pragma unroll
        for (int it = 0, c = tid; it < 2; it++, c += 256) {
            int kk = c >> 4, nc = (c & 15) * 8;
            cp16(sB + (st * 32 * LB + kk * LB + nc) * 2,
                 Bm + (size_t)(k0 + kk) * ldb + col0 + nc);
        }
        cpcommit();
    };

    issue(0, 0);
    int nk = K / 32;
    for (int i = 0; i < nk; i++) {
        int st = i & 1;
        cpwait0();
        __syncthreads();
        if (i + 1 < nk) issue(st ^ 1, (i + 1) * 32);
        const uint16_t* Ab = As[st];
        uint32_t sBst = sB + st * 32 * LB * 2;
        #pragma unroll
        for (int kk = 0; kk < 32; kk += 16) {
            uint32_t af[2][4];
            #pragma unroll
            for (int mt = 0; mt < 2; mt++) {
                const uint16_t* p = &Ab[(warpM * 32 + mt * 16 + g) * LA + kk + 2 * tg];
                af[mt][0] = *(const uint32_t*)p;
                af[mt][1] = *(const uint32_t*)(p + 8 * LA);
                af[mt][2] = *(const uint32_t*)(p + 8);
                af[mt][3] = *(const uint32_t*)(p + 8 * LA + 8);
            }
            #pragma unroll
            for (int p2 = 0; p2 < 4; p2++) {
                uint32_t bq[4];
                ldsm4t(bq, sBst + (uint32_t)((kk + koff) * LB + warpN * 64 + p2 * 16 + nsel) * 2);
                #pragma unroll
                for (int mt = 0; mt < 2; mt++) {
                    mma16816<HALF>(acc[mt][2 * p2], af[mt], bq[0], bq[1]);
                    mma16816<HALF>(acc[mt][2 * p2 + 1], af[mt], bq[2], bq[3]);
                }
            }
        }
        __syncthreads();
    }
    #pragma unroll
    for (int mt = 0; mt < 2; mt++)
        #pragma unroll
        for (int nt = 0; nt < 8; nt++) {
            int r = row0 + warpM * 32 + mt * 16 + g;
            int cc = col0 + warpN * 64 + nt * 8 + 2 * tg;
            #pragma unroll
            for (int hf = 0; hf < 2; hf++) {
                int rr = r + hf * 8;
                float v0 = acc[mt][nt][hf * 2], v1 = acc[mt][nt][hf * 2 + 1];
                long idx = (long)rr * ldc + cc;
                if (EPI == 2) {
                    v0 += bias[cc] + resid[idx];
                    v1 += bias[cc + 1] + resid[idx + 1];
                    *(float2*)((float*)Cp + idx) = make_float2(v0, v1);
                } else {
                    if (EPI == 3) {
                        v0 += bias[cc]; v1 += bias[cc + 1];
                        v0 = 0.5f * v0 * (1.0f + erff(v0 * 0.70710678f));
                        v1 = 0.5f * v1 * (1.0f + erff(v1 * 0.70710678f));
                    }
                    uint32_t pk;
                    if (HALF) {
                        __half2 t = __floats2half2_rn(v0, v1);
                        pk = *(uint32_t*)&t;
                    } else {
                        pk = packbf(v0, v1);
                    }
                    *(uint32_t*)((uint16_t*)Cp + idx) = pk;
                }
            }
        }
}

// ---------------- host ----------------
template <typename T>
static T* symaddr(const T& sym) {
    void* p = nullptr;
    cudaGetSymbolAddress(&p, sym);
    return (T*)p;
}

extern "C" void kernel_launch(void* const* d_in, const int* in_sizes, int n_in,
                              void* d_out, int out_size) {
    const float* x    = (const float*)d_in[0];
    const float* mask = (const float*)d_in[1];
    const float* Wqkv = (const float*)d_in[2];
    const float* Wout = (const float*)d_in[3];
    const float* bout = (const float*)d_in[4];
    const float* ln1g = (const float*)d_in[5];
    const float* ln1b = (const float*)d_in[6];
    const float* ln2g = (const float*)d_in[7];
    const float* ln2b = (const float*)d_in[8];
    const float* W1   = (const float*)d_in[9];
    const float* b1   = (const float*)d_in[10];
    const float* W2   = (const float*)d_in[11];
    const float* b2   = (const float*)d_in[12];

    bf16* h = (bf16*)symaddr(g_h);
    bf16* qkv = (bf16*)symaddr(g_qkv);
    bf16* attn = (bf16*)symaddr(g_attn);
    float* x1 = (float*)symaddr(g_x1);
    __half* h2h = (__half*)symaddr(g_h2h);
    __half* ffh = (__half*)symaddr(g_ffh);
    float* tk = (float*)symaddr(g_topk);
    uint32_t* mb = (uint32_t*)symaddr(g_mbits);
    bf16* wqkv = (bf16*)symaddr(g_Wqkv);
    bf16* wout = (bf16*)symaddr(g_Wout);
    __half* w1h = (__half*)symaddr(g_W1h);
    __half* w2h = (__half*)symaddr(g_W2h);

    cudaFuncSetAttribute(flash_kernel, cudaFuncAttributeMaxDynamicSharedMemorySize, FL_SMEM);

    cvt_kernel<<<(D_ * 3 * D_ + 255) / 256, 256>>>(Wqkv, wqkv, D_ * 3 * D_);
    cvt_kernel<<<(D_ * D_ + 255) / 256, 256>>>(Wout, wout, D_ * D_);
    cvth_kernel<<<(D_ * MLP_ + 255) / 256, 256>>>(W1, w1h, D_ * MLP_);
    cvth_kernel<<<(MLP_ * D_ + 255) / 256, 256>>>(W2, w2h, MLP_ * D_);
    maskbits_kernel<<<B_ * N_ * N_ / 256, 256>>>(mask, mb);
    ln_kernel<0><<<ROWS_, 128>>>(x, ln1g, ln1b, h);

    // qkv = h @ Wqkv  (bf16)
    gemm_k<0, false><<<dim3(12, 64), 256>>>(
        (const uint16_t*)h, (const uint16_t*)wqkv, qkv, D_, D_, 3 * D_, 3 * D_, nullptr, nullptr);
    flash_kernel<<<dim3(8, 64), 256, FL_SMEM>>>(qkv, mb, attn);
    topk0_kernel<<<B_, 1024>>>(qkv, mask, tk);
    prune_kernel<<<B_, 1024>>>(tk, (float*)d_out);
    // x1 = x + attn @ Wout + bout  (bf16)
    gemm_k<2, false><<<dim3(4, 64), 256>>>(
        (const uint16_t*)attn, (const uint16_t*)wout, x1, D_, D_, D_, D_, bout, x);
    ln_kernel<1><<<ROWS_, 128>>>(x1, ln2g, ln2b, h2h);
    // ff = gelu(h2 @ W1 + b1)  (fp16)
    gemm_k<3, true><<<dim3(16, 64), 256>>>(
        (const uint16_t*)h2h, (const uint16_t*)w1h, ffh, D_, D_, MLP_, MLP_, b1, nullptr);
    // out = x1 + ff @ W2 + b2  (fp16)
    gemm_k<2, true><<<dim3(4, 64), 256>>>(
        (const uint16_t*)ffh, (const uint16_t*)w2h, (float*)d_out, MLP_, MLP_, D_, D_, b2, x1);
}